// round 12
// baseline (speedup 1.0000x reference)
#include <cuda_runtime.h>
#include <math.h>

#define BB 4096
#define TT 750
#define WIN 11
#define NSN (TT * WIN)          // 8250
#define NCHUNK 256              // row chunks (16 rows each)
#define CROWS 16
#define TILE_T 250              // t-columns per tile (3 tiles = 750)
#define NOUT (TT * 6)           // 4500 S_d[t] slots
#define MAIN_GRID 512
#define NS_SKIP_THRESH 176.0f   // exp(-88): contribution negligible vs loss ~12.5

// Scratch (static device globals, zero-init; k_M tail re-zeroes for replay)
__device__ float g_S[NOUT];          // S_d[t] accumulators (atomicAdd targets)
__device__ float g_E[31];            // edge (scrambled-pad) sums
__device__ float g_ns[NSN];
__device__ unsigned int g_mask[TT];  // bits w != 6 only
__device__ unsigned int g_any;       // OR of all masks
__device__ float g_bpart[MAIN_GRID];
__device__ unsigned int g_done;

// ---------------------------------------------------------------------------
// Kernel A: S_d[t] = sum_b (a[b,t]-a[b,t+d])^2, d=1..6, via direct atomicAdd.
// Block = (chunk z of 16 rows) x (t-tile of 250 cols). 16x256 smem tile
// (6-col halo), one sync, column-stationary register accumulation, then 6
// REDG adds per thread. S slots with t+d>749 receive garbage but are
// provably never consumed downstream (k_R guards t+d<=749).
// Order-nondeterminism of the float atomics is harmless: g_S only feeds the
// threshold compare (margin ~683 vs 176) — final output stays fixed-order.
// Edge pairs per reference tile-reshape pad:
//   front(b,j)=a[(6b+j)%B,0]; back(b,j)=a[(6b+j-755)%B,T-1].
// ---------------------------------------------------------------------------
__global__ __launch_bounds__(256) void k_ns_part(const float* __restrict__ a) {
    __shared__ float s[CROWS][256];
    const int tile = blockIdx.x % 3;
    const int z    = blockIdx.x / 3;
    const int t0   = tile * TILE_T;
    const int b0   = z * CROWS;
    const int tid  = threadIdx.x;

    // Stage (coalesced; halo cols >= 750 zeroed — never consumed)
    const int gc = t0 + tid;
    const bool cv = (gc < TT);
#pragma unroll
    for (int r = 0; r < CROWS; r++)
        s[r][tid] = cv ? a[(size_t)(b0 + r) * TT + gc] : 0.0f;
    __syncthreads();

    // Column-stationary accumulation
    float S[6] = {0.f, 0.f, 0.f, 0.f, 0.f, 0.f};
    const bool act = (tid < TILE_T);
    if (act) {
#pragma unroll 8
        for (int r = 0; r < CROWS; r++) {
            const float at = s[r][tid];
#pragma unroll
            for (int d = 1; d <= 6; d++) {
                const float df = at - s[r][tid + d];
                S[d - 1] += df * df;
            }
        }
    }

    // Edge partials -> atomicAdd to g_E
    if (tile == 0 && tid < 21) {
        int et = 0, ew = 0, acc = 0;
        for (int t = 0; t < 6; t++) {
            const int c = 6 - t;
            if (tid < acc + c) { et = t; ew = tid - acc; break; }
            acc += c;
        }
        const int j = et + ew;          // j < 6
        float eacc = 0.0f;
        for (int r0 = 0; r0 < CROWS; r0 += 8) {
            float pv[8];
#pragma unroll
            for (int k = 0; k < 8; k++)
                pv[k] = __ldg(a + (size_t)((6 * (b0 + r0 + k) + j) & (BB - 1)) * TT);
#pragma unroll
            for (int k = 0; k < 8; k++) {
                const float d = s[r0 + k][et] - pv[k];
                eacc += d * d;
            }
        }
        atomicAdd(&g_E[tid], eacc);
    } else if (tile == 2 && tid < 10) {
        int et = 0, ew = 0, acc = 0;
        for (int t = 746; t < 750; t++) {
            const int c = t - 745;
            if (tid < acc + c) { et = t; ew = (756 - t) + (tid - acc); break; }
            acc += c;
        }
        const int j = et + ew;          // j >= 756
        const int col = et - t0;        // 246..249
        float eacc = 0.0f;
        for (int r0 = 0; r0 < CROWS; r0 += 8) {
            float pv[8];
#pragma unroll
            for (int k = 0; k < 8; k++)
                pv[k] = __ldg(a + (size_t)((6 * (b0 + r0 + k) + (j - 755)) & (BB - 1)) * TT + (TT - 1));
#pragma unroll
            for (int k = 0; k < 8; k++) {
                const float d = s[r0 + k][col] - pv[k];
                eacc += d * d;
            }
        }
        atomicAdd(&g_E[21 + tid], eacc);
    }

    // Accumulate into tiny global S array (6 consecutive slots per thread)
    if (act) {
        const int t = t0 + tid;
        float* __restrict__ p = g_S + t * 6;
#pragma unroll
        for (int d = 0; d < 6; d++) atomicAdd(p + d, S[d]);
    }
}

// ---------------------------------------------------------------------------
// Kernel R: build g_ns[t][11] + per-t mask + g_any from the 18KB g_S/g_E
// (L2-resident). Mask EXCLUDES w=6: that term is identically zero since
// j=t+6 is always interior so d2 == |a2[i,t]-a2[i,t]| == 0 for any input.
// ---------------------------------------------------------------------------
__global__ __launch_bounds__(256) void k_reduce_mask() {
    const int tid = threadIdx.x;
    const int t = blockIdx.x * TILE_T + tid;
    if (tid < TILE_T && t < TT) {
        unsigned m = 0;
#pragma unroll
        for (int w = 0; w < WIN; w++) {
            float v;
            if (w == 6) {
                v = 0.0f;
            } else if (w > 6) {                 // d = w-6, S_d[t]
                if (t + w < 756) v = __ldg(&g_S[t * 6 + (w - 6) - 1]);
                else             v = __ldg(&g_E[21 + (t - 746) * (t - 745) / 2 + (w - (756 - t))]);
            } else {                            // d = 6-w, S_d[t-d]
                const int d = 6 - w;
                if (t - d >= 0) v = __ldg(&g_S[(t - d) * 6 + d - 1]);
                else            v = __ldg(&g_E[t * (13 - t) / 2 + w]);
            }
            g_ns[t * WIN + w] = v;
            if (w != 6 && v <= NS_SKIP_THRESH) m |= (1u << w);
        }
        g_mask[t] = m;
        if (m) atomicOr(&g_any, m);
    }
}

// ---------------------------------------------------------------------------
// Kernel M: main pass + fused final reduction + scratch reset.
// Fast path (g_any==0, the provable common case): term1 == 0 exactly, and
// term2 needs NO row structure: 0.1/B * sum over ALL elements of (a-a2)^2.
// -> whole-array grid-stride float4 stream (pure BW-bound).
// Slow path: faithful filtered evaluation, warp-per-row.
// Block 0 zeroes g_S/g_E for the next replay (safe: R already consumed them);
// last block zeroes g_any/g_done after everyone has read them.
// ---------------------------------------------------------------------------
__global__ __launch_bounds__(256) void k_main(const float* __restrict__ a,
                                              const float* __restrict__ a2,
                                              float* __restrict__ out) {
    const int tid = threadIdx.x, lane = tid & 31, warp = tid >> 5;

    if (blockIdx.x == 0) {          // reset accumulators for next graph replay
        for (int k = tid; k < NOUT; k += 256) g_S[k] = 0.0f;
        if (tid < 31) g_E[tid] = 0.0f;
    }

    float acc1 = 0.0f, acc2 = 0.0f;
    const bool fast = (__ldg(&g_any) == 0u);

    if (fast) {
        const float4* __restrict__ pa  = (const float4*)a;    // base 256B-aligned
        const float4* __restrict__ pa2 = (const float4*)a2;
        const int N4 = (BB * TT) / 4;                         // 768000
        const int stride = MAIN_GRID * 256;
#pragma unroll 3
        for (int idx = blockIdx.x * 256 + tid; idx < N4; idx += stride) {
            const float4 x = pa[idx];
            const float4 y = pa2[idx];
            const float d0 = x.x - y.x, d1 = x.y - y.y;
            const float d2 = x.z - y.z, d3 = x.w - y.w;
            acc2 += d0 * d0 + d1 * d1 + d2 * d2 + d3 * d3;
        }
    } else {
        const int i = blockIdx.x * 8 + warp;
        const float* __restrict__ ra  = a  + (size_t)i * TT;
        const float* __restrict__ ra2 = a2 + (size_t)i * TT;
        for (int t = lane; t < TT; t += 32) {
            const float av  = ra[t];
            const float a2v = ra2[t];
            const float dd = av - a2v;
            acc2 += dd * dd;

            unsigned m = g_mask[t];
            while (m) {
                const int w = __ffs(m) - 1;
                m &= m - 1;
                const int j = t + w;
                float a3w;
                if (j < 6)            a3w = a2[(size_t)((6 * i + j) & (BB - 1)) * TT];
                else if (j < TT + 6)  a3w = ra2[j - 6];
                else                  a3w = a2[(size_t)((6 * i + (j - 755)) & (BB - 1)) * TT + (TT - 1)];
                const float d2 = fabsf(a2v - a3w);
                if (d2 != 0.0f) {
                    float mx = -3.0e38f;
#pragma unroll
                    for (int w2 = 0; w2 < WIN; w2++) {
                        const int j2 = t + w2;
                        float a4w;
                        if (j2 < 6)           a4w = a[(size_t)((6 * i + j2) & (BB - 1)) * TT];
                        else if (j2 < TT + 6) a4w = ra[j2 - 6];
                        else                  a4w = a[(size_t)((6 * i + (j2 - 755)) & (BB - 1)) * TT + (TT - 1)];
                        const float tv = a[(size_t)((11 * i + w2) & (BB - 1)) * TT + t];
                        mx = fmaxf(mx, tv - a4w);
                    }
                    const float g = mx * mx;             // E_G = 1
                    const float ns = g_ns[t * WIN + w];
                    const float expo = fmaxf(ns, g);     // relu(ns-g)+g
                    acc1 += __expf(-0.5f * expo) * d2;   // SIGMA = 1
                }
            }
        }
    }

    float v = acc1 + 0.1f * acc2;                        // E_THETA = 0.1
#pragma unroll
    for (int off = 16; off; off >>= 1) v += __shfl_down_sync(0xffffffffu, v, off);

    __shared__ float sw[8];
    __shared__ bool s_last;
    if (lane == 0) sw[warp] = v;
    __syncthreads();
    if (tid == 0) {
        float bs = 0.0f;
#pragma unroll
        for (int k = 0; k < 8; k++) bs += sw[k];
        g_bpart[blockIdx.x] = bs;
        __threadfence();
        s_last = (atomicAdd(&g_done, 1u) == (unsigned)(gridDim.x - 1));
    }
    __syncthreads();

    if (s_last) {
        __shared__ double dred[256];
        double s = (double)g_bpart[tid] + (double)g_bpart[tid + 256];
        dred[tid] = s;
        __syncthreads();
        for (int st = 128; st; st >>= 1) {
            if (tid < st) dred[tid] += dred[tid + st];
            __syncthreads();
        }
        if (tid == 0) {
            out[0] = (float)(dred[0] / (double)BB);      // E_ALPHA = 1
            g_any = 0u;                                  // all blocks read it already
            g_done = 0u;                                 // reset for graph replay
        }
    }
}

// ---------------------------------------------------------------------------
extern "C" void kernel_launch(void* const* d_in, const int* in_sizes, int n_in,
                              void* d_out, int out_size) {
    (void)in_sizes; (void)n_in; (void)out_size;
    const float* a  = (const float*)d_in[0];   // actioness   [4096,750]
    const float* a2 = (const float*)d_in[1];   // actioness_2 [4096,750]
    float* out = (float*)d_out;

    k_ns_part<<<NCHUNK * 3, 256>>>(a);
    k_reduce_mask<<<3, 256>>>();
    k_main<<<MAIN_GRID, 256>>>(a, a2, out);
}

// round 13
// speedup vs baseline: 1.6559x; 1.6559x over previous
#include <cuda_runtime.h>
#include <math.h>

#define BB 4096
#define TT 750
#define WIN 11
#define NSN (TT * WIN)          // 8250
#define NCHUNK 256              // row chunks (16 rows each)
#define CROWS 16
#define TILE_T 250              // t-columns per tile (3 tiles = 750)
#define NOUT (TT * 6)           // 4500 S_d[t] outputs
#define A_GRID (NCHUNK * 3)     // 768
#define MAIN_GRID 512
#define NS_SKIP_THRESH 176.0f   // exp(-88): contribution negligible vs loss ~12.5

// Scratch (static device globals; no allocation allowed)
__device__ float g_part[(size_t)NCHUNK * NOUT];     // [z][o], 4.6 MB, o = t*6+(d-1)
__device__ float g_edge_part[31 * NCHUNK];          // [e][z]
__device__ float g_apart[A_GRID];                   // per-A-block sum of (a-a2)^2
__device__ float g_ns[NSN];
__device__ unsigned int g_mask[TT];                 // bits w != 6 only
__device__ unsigned int g_any;                      // OR of all masks
__device__ float g_bpart[MAIN_GRID];
__device__ unsigned int g_done;                     // zero-init; last block resets

// ---------------------------------------------------------------------------
// Kernel A: S_d partials (d=1..6) + FUSED term-2 partial sum.
// Block = (chunk z of 16 rows) x (t-tile of 250 cols). 16x256 smem tile
// (6-col halo), one sync. a2 tile is streamed into registers BEFORE the smem
// compute so its DRAM latency hides under the S accumulation.
// Partials stored TRANSPOSED [z][o]: 6 consecutive floats/thread (coalesced).
// Edge (scrambled-pad) partials per reference tile-reshape:
//   front(b,j)=a[(6b+j)%B,0]; back(b,j)=a[(6b+j-755)%B,T-1].
// ---------------------------------------------------------------------------
__global__ __launch_bounds__(256) void k_ns_part(const float* __restrict__ a,
                                                  const float* __restrict__ a2) {
    __shared__ float s[CROWS][256];
    const int tile = blockIdx.x % 3;
    const int z    = blockIdx.x / 3;
    const int t0   = tile * TILE_T;
    const int b0   = z * CROWS;
    const int tid  = threadIdx.x;

    // Stage a (coalesced; halo cols >= 750 zeroed — never consumed)
    const int gc = t0 + tid;
    const bool cv = (gc < TT);
#pragma unroll
    for (int r = 0; r < CROWS; r++)
        s[r][tid] = cv ? a[(size_t)(b0 + r) * TT + gc] : 0.0f;

    // Issue a2 stream loads early (latency hidden under smem compute below)
    const bool act = (tid < TILE_T);
    float v2[CROWS];
    if (act) {
#pragma unroll
        for (int r = 0; r < CROWS; r++)
            v2[r] = a2[(size_t)(b0 + r) * TT + gc];
    }
    __syncthreads();

    // Column-stationary S accumulation + fused diff^2
    float S[6] = {0.f, 0.f, 0.f, 0.f, 0.f, 0.f};
    float acc2 = 0.0f;
    if (act) {
#pragma unroll 8
        for (int r = 0; r < CROWS; r++) {
            const float at = s[r][tid];
#pragma unroll
            for (int d = 1; d <= 6; d++) {
                const float df = at - s[r][tid + d];
                S[d - 1] += df * df;
            }
            const float dd = at - v2[r];
            acc2 += dd * dd;
        }
    }

    // Edge partials
    if (tile == 0 && tid < 21) {
        int et = 0, ew = 0, acc = 0;
        for (int t = 0; t < 6; t++) {
            const int c = 6 - t;
            if (tid < acc + c) { et = t; ew = tid - acc; break; }
            acc += c;
        }
        const int j = et + ew;          // j < 6
        float eacc = 0.0f;
        for (int r0 = 0; r0 < CROWS; r0 += 8) {
            float pv[8];
#pragma unroll
            for (int k = 0; k < 8; k++)
                pv[k] = __ldg(a + (size_t)((6 * (b0 + r0 + k) + j) & (BB - 1)) * TT);
#pragma unroll
            for (int k = 0; k < 8; k++) {
                const float d = s[r0 + k][et] - pv[k];
                eacc += d * d;
            }
        }
        g_edge_part[tid * NCHUNK + z] = eacc;
    } else if (tile == 2 && tid < 10) {
        int et = 0, ew = 0, acc = 0;
        for (int t = 746; t < 750; t++) {
            const int c = t - 745;
            if (tid < acc + c) { et = t; ew = (756 - t) + (tid - acc); break; }
            acc += c;
        }
        const int j = et + ew;          // j >= 756
        const int col = et - t0;        // 246..249
        float eacc = 0.0f;
        for (int r0 = 0; r0 < CROWS; r0 += 8) {
            float pv[8];
#pragma unroll
            for (int k = 0; k < 8; k++)
                pv[k] = __ldg(a + (size_t)((6 * (b0 + r0 + k) + (j - 755)) & (BB - 1)) * TT + (TT - 1));
#pragma unroll
            for (int k = 0; k < 8; k++) {
                const float d = s[r0 + k][col] - pv[k];
                eacc += d * d;
            }
        }
        g_edge_part[(21 + tid) * NCHUNK + z] = eacc;
    }

    // Coalesced transposed S store
    if (act) {
        const int t = t0 + tid;
        float* __restrict__ p = g_part + (size_t)z * NOUT + t * 6;
#pragma unroll
        for (int d = 0; d < 6; d++) p[d] = S[d];
    }

    // Block-reduce diff^2 partial (fixed order within block -> deterministic)
    const int lane = tid & 31, warp = tid >> 5;
#pragma unroll
    for (int off = 16; off; off >>= 1) acc2 += __shfl_down_sync(0xffffffffu, acc2, off);
    __shared__ float sw[8];
    if (lane == 0) sw[warp] = acc2;
    __syncthreads();
    if (tid == 0) {
        float bs = 0.0f;
#pragma unroll
        for (int k = 0; k < 8; k++) bs += sw[k];
        g_apart[blockIdx.x] = bs;
    }
}

// ---------------------------------------------------------------------------
// Kernel R: reduce partials over z -> g_ns[t][11] + per-t mask + g_any.
// 21 blocks x 512 threads; the 252 outputs per block (36 t + 6-t halo, x6 d)
// are each summed by TWO threads (z halves) to halve the dependent-load chain.
// Mask EXCLUDES w=6: that term is identically zero (j=t+6 always interior, so
// d2 == |a2[i,t]-a2[i,t]| == 0 for any input). Fixed-order -> deterministic.
// ---------------------------------------------------------------------------
__global__ __launch_bounds__(512) void k_reduce_mask() {
    const int t0 = blockIdx.x * 36;
    const int o0 = t0 * 6 - 36;
    const int tid = threadIdx.x, lane = tid & 31, warp = tid >> 5;
    const int half = tid >> 8;          // 0 or 1
    const int ol = tid & 255;
    __shared__ float sSh[2][256];
    __shared__ float sE[31];

    float acc = 0.0f;
    const int o = o0 + ol;
    if (ol < 252 && o >= 0 && o < NOUT) {
        const float* __restrict__ p = g_part + o + (size_t)half * 128 * NOUT;
#pragma unroll 8
        for (int zz = 0; zz < 128; zz++) acc += p[(size_t)zz * NOUT];
    }
    sSh[half][ol] = acc;

    // Edge sums (blocks 0 and 20); warp-per-e, coalesced over z
    if (blockIdx.x == 0) {
        for (int e = warp; e < 21; e += 16) {
            const float* __restrict__ p = g_edge_part + (size_t)e * NCHUNK;
            float v = 0.0f;
#pragma unroll
            for (int k = 0; k < 8; k++) v += p[lane + 32 * k];
#pragma unroll
            for (int off = 16; off; off >>= 1) v += __shfl_down_sync(0xffffffffu, v, off);
            if (lane == 0) sE[e] = v;
        }
    } else if (blockIdx.x == 20) {
        for (int e = 21 + warp; e < 31; e += 16) {
            const float* __restrict__ p = g_edge_part + (size_t)e * NCHUNK;
            float v = 0.0f;
#pragma unroll
            for (int k = 0; k < 8; k++) v += p[lane + 32 * k];
#pragma unroll
            for (int off = 16; off; off >>= 1) v += __shfl_down_sync(0xffffffffu, v, off);
            if (lane == 0) sE[e] = v;
        }
    }
    __syncthreads();

    if (tid < 36) {
        const int t = t0 + tid;
        if (t < TT) {
            unsigned m = 0;
#pragma unroll
            for (int w = 0; w < WIN; w++) {
                float v;
                if (w == 6) {
                    v = 0.0f;
                } else if (w > 6) {                     // d = w-6, S_d[t]
                    const int x = (t * 6 + (w - 6) - 1) - o0;
                    if (t + w < 756) v = sSh[0][x] + sSh[1][x];
                    else             v = sE[21 + (t - 746) * (t - 745) / 2 + (w - (756 - t))];
                } else {                                // d = 6-w, S_d[t-d]
                    const int d = 6 - w;
                    const int x = ((t - d) * 6 + d - 1) - o0;
                    if (t - d >= 0) v = sSh[0][x] + sSh[1][x];
                    else            v = sE[t * (13 - t) / 2 + w];
                }
                g_ns[t * WIN + w] = v;
                if (w != 6 && v <= NS_SKIP_THRESH) m |= (1u << w);
            }
            g_mask[t] = m;
            if (m) atomicOr(&g_any, m);
        }
    }
}

// ---------------------------------------------------------------------------
// Kernel M: term1 (only when g_any != 0; faithful warp-per-row path) + fused
// final reduction. term2 partials already live in g_apart (from kernel A).
// Fast path (g_any==0, provable common case): zero memory work per block.
// Final (last block, fixed order): out = (sum bpart + 0.1*sum apart)/B.
// ---------------------------------------------------------------------------
__global__ __launch_bounds__(256) void k_main(const float* __restrict__ a,
                                              const float* __restrict__ a2,
                                              float* __restrict__ out) {
    const int tid = threadIdx.x, lane = tid & 31, warp = tid >> 5;

    float acc1 = 0.0f;
    if (__ldg(&g_any) != 0u) {
        const int i = blockIdx.x * 8 + warp;
        const float* __restrict__ ra  = a  + (size_t)i * TT;
        const float* __restrict__ ra2 = a2 + (size_t)i * TT;
        for (int t = lane; t < TT; t += 32) {
            const float a2v = ra2[t];
            unsigned m = g_mask[t];
            while (m) {
                const int w = __ffs(m) - 1;
                m &= m - 1;
                const int j = t + w;
                float a3w;
                if (j < 6)            a3w = a2[(size_t)((6 * i + j) & (BB - 1)) * TT];
                else if (j < TT + 6)  a3w = ra2[j - 6];
                else                  a3w = a2[(size_t)((6 * i + (j - 755)) & (BB - 1)) * TT + (TT - 1)];
                const float d2 = fabsf(a2v - a3w);
                if (d2 != 0.0f) {
                    float mx = -3.0e38f;
#pragma unroll
                    for (int w2 = 0; w2 < WIN; w2++) {
                        const int j2 = t + w2;
                        float a4w;
                        if (j2 < 6)           a4w = a[(size_t)((6 * i + j2) & (BB - 1)) * TT];
                        else if (j2 < TT + 6) a4w = ra[j2 - 6];
                        else                  a4w = a[(size_t)((6 * i + (j2 - 755)) & (BB - 1)) * TT + (TT - 1)];
                        const float tv = a[(size_t)((11 * i + w2) & (BB - 1)) * TT + t];
                        mx = fmaxf(mx, tv - a4w);
                    }
                    const float g = mx * mx;             // E_G = 1
                    const float ns = g_ns[t * WIN + w];
                    const float expo = fmaxf(ns, g);     // relu(ns-g)+g
                    acc1 += __expf(-0.5f * expo) * d2;   // SIGMA = 1
                }
            }
        }
    }

#pragma unroll
    for (int off = 16; off; off >>= 1) acc1 += __shfl_down_sync(0xffffffffu, acc1, off);

    __shared__ float sw[8];
    __shared__ bool s_last;
    if (lane == 0) sw[warp] = acc1;
    __syncthreads();
    if (tid == 0) {
        float bs = 0.0f;
#pragma unroll
        for (int k = 0; k < 8; k++) bs += sw[k];
        g_bpart[blockIdx.x] = bs;
        __threadfence();
        s_last = (atomicAdd(&g_done, 1u) == (unsigned)(gridDim.x - 1));
    }
    __syncthreads();

    if (s_last) {
        __shared__ double dred[256];
        double s = (double)g_bpart[tid] + (double)g_bpart[tid + 256];
        s += 0.1 * ((double)g_apart[tid] + (double)g_apart[tid + 256] +
                    (double)g_apart[tid + 512]);        // E_THETA = 0.1
        dred[tid] = s;
        __syncthreads();
        for (int st = 128; st; st >>= 1) {
            if (tid < st) dred[tid] += dred[tid + st];
            __syncthreads();
        }
        if (tid == 0) {
            out[0] = (float)(dred[0] / (double)BB);      // E_ALPHA = 1
            g_any = 0u;                                  // all blocks already read it
            g_done = 0u;                                 // reset for graph replay
        }
    }
}

// ---------------------------------------------------------------------------
extern "C" void kernel_launch(void* const* d_in, const int* in_sizes, int n_in,
                              void* d_out, int out_size) {
    (void)in_sizes; (void)n_in; (void)out_size;
    const float* a  = (const float*)d_in[0];   // actioness   [4096,750]
    const float* a2 = (const float*)d_in[1];   // actioness_2 [4096,750]
    float* out = (float*)d_out;

    k_ns_part<<<A_GRID, 256>>>(a, a2);
    k_reduce_mask<<<21, 512>>>();
    k_main<<<MAIN_GRID, 256>>>(a, a2, out);
}